// round 6
// baseline (speedup 1.0000x reference)
#include <cuda_runtime.h>
#include <cstdint>

// Problem constants
#define BB   64
#define DD   920
#define NSMP 920
#define KK   32
#define TOT  (BB * NSMP * DD)   // 54,169,600
#define HALF (TOT / 2)          // 27,084,800

// Scratch (static device globals -> no runtime allocation)
__device__ int   g_cnt[BB * KK * DD];     // 7.5 MB
__device__ float g_thr[BB];

// ---------------------------------------------------------------------------
// threefry2x32 (JAX-exact), both outputs returned
// ---------------------------------------------------------------------------
__device__ __forceinline__ unsigned rotl32(unsigned x, int r) {
    return __funnelshift_l(x, x, r);
}

__device__ __forceinline__ uint2 threefry(unsigned c0, unsigned c1) {
    const unsigned ks0 = 0u, ks1 = 1u, ks2 = 0x1BD11BDAu ^ 0u ^ 1u;
    unsigned x0 = c0 + ks0;
    unsigned x1 = c1 + ks1;
#define RND(r) { x0 += x1; x1 = rotl32(x1, r); x1 ^= x0; }
    RND(13) RND(15) RND(26) RND(6)   x0 += ks1; x1 += ks2 + 1u;
    RND(17) RND(29) RND(16) RND(24)  x0 += ks2; x1 += ks0 + 2u;
    RND(13) RND(15) RND(26) RND(6)   x0 += ks0; x1 += ks1 + 3u;
    RND(17) RND(29) RND(16) RND(24)  x0 += ks1; x1 += ks2 + 4u;
    RND(13) RND(15) RND(26) RND(6)   x0 += ks2; x1 += ks0 + 5u;
#undef RND
    return make_uint2(x0, x1);
}

// bits -> float normal (JAX float32 path; Giles erfinv as in XLA)
__device__ __forceinline__ float bits_to_normal(unsigned b) {
    const float LO = -0.99999994f;  // nextafterf(-1,0)
    float f = __uint_as_float((b >> 9) | 0x3f800000u) - 1.0f;
    float u = fmaxf(LO, f * 2.0f + LO);
    float x2 = u * u;
    float w = -__logf(1.0f - x2);
    float p;
    if (w < 5.0f) {
        w -= 2.5f;
        p = 2.81022636e-08f;
        p = fmaf(p, w, 3.43273939e-07f);
        p = fmaf(p, w, -3.5233877e-06f);
        p = fmaf(p, w, -4.39150654e-06f);
        p = fmaf(p, w, 0.00021858087f);
        p = fmaf(p, w, -0.00125372503f);
        p = fmaf(p, w, -0.00417768164f);
        p = fmaf(p, w, 0.246640727f);
        p = fmaf(p, w, 1.50140941f);
    } else {
        w = sqrtf(w) - 3.0f;
        p = -0.000200214257f;
        p = fmaf(p, w, 0.000100950558f);
        p = fmaf(p, w, 0.00134934322f);
        p = fmaf(p, w, -0.00367342844f);
        p = fmaf(p, w, 0.00573950773f);
        p = fmaf(p, w, -0.0076224613f);
        p = fmaf(p, w, 0.00943887047f);
        p = fmaf(p, w, 1.00167406f);
        p = fmaf(p, w, 2.83297682f);
    }
    return 1.41421356f * (p * u);
}

// ---------------------------------------------------------------------------
// Kernel 0: zero the count histogram (int4) + per-b threshold, one launch.
// Blocks [0, ZB) zero; blocks [ZB, ZB+2) compute thresholds (32 warps each).
// ---------------------------------------------------------------------------
#define ZCNT ((BB * KK * DD) / 4)        // 471,040 int4 stores
#define ZB   ((ZCNT + 1023) / 1024)      // 460

__global__ void prep_kernel(const float* __restrict__ wa) {
    if (blockIdx.x < ZB) {
        int i = blockIdx.x * 1024 + threadIdx.x;
        if (i < ZCNT) reinterpret_cast<int4*>(g_cnt)[i] = make_int4(0, 0, 0, 0);
        return;
    }
    int gw = (blockIdx.x - ZB) * 32 + (threadIdx.x >> 5);
    int lane = threadIdx.x & 31;
    if (gw >= BB) return;
    const float* row = wa + gw * DD;
    float v[29];
#pragma unroll
    for (int s = 0; s < 29; s++) {
        int d = s * 32 + lane;
        v[s] = (d < DD) ? row[d] : -1e30f;
    }
    float tl = -1.0f, th = 2.0f;
    for (int it = 0; it < 28; it++) {
        float t = 0.5f * (tl + th);
        int lc = 0;
#pragma unroll
        for (int s = 0; s < 29; s++) lc += (v[s] > t) ? 1 : 0;
        int c = __reduce_add_sync(0xffffffffu, lc);
        if (c > 45) tl = t; else th = t;
    }
    if (lane == 0) g_thr[gw] = 0.5f * (tl + th);
}

// ---------------------------------------------------------------------------
// Per-row top-32 pipeline: threshold search, compact, 64-wide bitonic sort,
// rank by index, atomic histogram update.  key[] = this warp's smem slice.
// ---------------------------------------------------------------------------
__device__ __forceinline__ void process_row(float (&v)[29], int b, int lane,
                                            unsigned long long* key) {
    float t = g_thr[b];
    float tl = -8.0f, th = 8.0f;
    int c = 0;
    for (int it = 0; it < 60; it++) {
        int lc = 0;
#pragma unroll
        for (int s = 0; s < 29; s++) lc += (v[s] > t) ? 1 : 0;
        c = __reduce_add_sync(0xffffffffu, lc);
        if (c >= 32 && c <= 64) break;
        if (c < 32) th = t; else tl = t;
        t = 0.5f * (tl + th);
    }

    // compact candidates as (ordered_float << 10) | (1023 - d)
    int base = 0;
#pragma unroll
    for (int s = 0; s < 29; s++) {
        bool p = v[s] > t;
        unsigned bal = __ballot_sync(0xffffffffu, p);
        if (p) {
            int pos = base + __popc(bal & ((1u << lane) - 1u));
            if (pos < 64) {
                int d = s * 32 + lane;
                unsigned ub = __float_as_uint(v[s]);
                ub = (ub & 0x80000000u) ? ~ub : (ub | 0x80000000u);
                key[pos] = (((unsigned long long)ub) << 10) |
                           (unsigned long long)(1023 - d);
            }
        }
        base += __popc(bal);
    }
    __syncwarp();

    unsigned long long v0 = (lane < c) ? key[lane] : 0ull;
    unsigned long long v1 = (lane + 32 < c) ? key[lane + 32] : 0ull;

    // bitonic sort, descending, over 64 elements (pos = r*32 + lane)
#pragma unroll
    for (int k = 2; k <= 64; k <<= 1) {
#pragma unroll
        for (int j = k >> 1; j > 0; j >>= 1) {
            if (j == 32) {  // pair (lane, 32+lane), keep max low
                unsigned long long mx = v0 > v1 ? v0 : v1;
                unsigned long long mn = v0 > v1 ? v1 : v0;
                v0 = mx; v1 = mn;
            } else {
                {
                    unsigned long long o = __shfl_xor_sync(0xffffffffu, v0, j);
                    bool km = ((lane & k) == 0);
                    bool lo2 = ((lane & j) == 0);
                    v0 = (km == lo2) ? (v0 > o ? v0 : o) : (v0 < o ? v0 : o);
                }
                {
                    unsigned long long o = __shfl_xor_sync(0xffffffffu, v1, j);
                    int p2 = 32 + lane;
                    bool km = ((p2 & k) == 0);
                    bool lo2 = ((lane & j) == 0);
                    v1 = (km == lo2) ? (v1 > o ? v1 : o) : (v1 < o ? v1 : o);
                }
            }
        }
    }

    // top-32 in v0; recover index, sort ascending; lane == rank after sort
    int d = 1023 - (int)(v0 & 1023ull);
#pragma unroll
    for (int k = 2; k <= 32; k <<= 1) {
#pragma unroll
        for (int j = k >> 1; j > 0; j >>= 1) {
            int o = __shfl_xor_sync(0xffffffffu, d, j);
            bool up = ((lane & k) == 0);
            bool lo2 = ((lane & j) == 0);
            d = (up == lo2) ? (d < o ? d : o) : (d > o ? d : o);
        }
    }
    atomicAdd(&g_cnt[(b * KK + lane) * DD + d], 1);
}

// ---------------------------------------------------------------------------
// Fused kernel: each warp generates noise for rows (b, n) AND (b+32, n) from
// single threefry calls (the (j, j+HALF) pairing maps exactly onto this row
// pair), then runs the top-32 pipeline on both rows.  No noise DRAM traffic.
// ---------------------------------------------------------------------------
__global__ void __launch_bounds__(256) ftopk_kernel(const float* __restrict__ wa) {
    __shared__ float s_waA[DD];
    __shared__ float s_waB[DD];
    __shared__ float s_vB[8][29][32];
    __shared__ unsigned long long s_key[8][64];

    int b = blockIdx.y;                 // 0..31 (pair: b and b+32)
    int warpid = threadIdx.x >> 5;
    int lane = threadIdx.x & 31;
    for (int i = threadIdx.x; i < DD; i += 256) {
        s_waA[i] = wa[b * DD + i];
        s_waB[i] = wa[(b + 32) * DD + i];
    }
    __syncthreads();

    int n = blockIdx.x * 8 + warpid;    // gridDim.x = 115 -> n in [0,920)
    unsigned rowbase = (unsigned)((b * NSMP + n) * DD);  // < HALF (b < 32)

    // Generate both rows' perturbed values: one threefry per (d) yields the
    // noise for (b,n,d) in .x and (b+32,n,d) in .y  (JAX iota/split pairing).
    float vA[29];
#pragma unroll
    for (int s = 0; s < 29; s++) {
        int d = s * 32 + lane;
        if (d < DD) {
            unsigned i = rowbase + (unsigned)d;
            uint2 r = threefry(i, i + (unsigned)HALF);
            vA[s] = s_waA[d] + 0.1f * bits_to_normal(r.x);
            s_vB[warpid][s][lane] = s_waB[d] + 0.1f * bits_to_normal(r.y);
        } else {
            vA[s] = -3.0e38f;
            s_vB[warpid][s][lane] = -3.0e38f;
        }
    }
    __syncwarp();

    process_row(vA, b, lane, s_key[warpid]);

    float vB[29];
#pragma unroll
    for (int s = 0; s < 29; s++) vB[s] = s_vB[warpid][s][lane];
    __syncwarp();

    process_row(vB, b + 32, lane, s_key[warpid]);
}

// ---------------------------------------------------------------------------
// Final: s = (cnt . wa) / 920, then bbox -> out (b, k, 4)
// ---------------------------------------------------------------------------
__global__ void final_kernel(const float* __restrict__ wa, float* __restrict__ out) {
    __shared__ float s_wa[DD];
    int b = blockIdx.x;
    int warpid = threadIdx.x >> 5;
    int lane = threadIdx.x & 31;
    for (int i = threadIdx.x; i < DD; i += 256) s_wa[i] = wa[b * DD + i];
    __syncthreads();
    for (int i = warpid; i < KK; i += 8) {
        const int* cr = &g_cnt[(b * KK + i) * DD];
        float acc = 0.0f;
        for (int d = lane; d < DD; d += 32) acc += (float)cr[d] * s_wa[d];
#pragma unroll
        for (int o = 16; o; o >>= 1) acc += __shfl_xor_sync(0xffffffffu, acc, o);
        if (lane == 0) {
            float sv = acc / 920.0f;
            float r  = floorf(sv / 40.0f);
            float cc = sv - 40.0f * r;           // jnp.mod(sv, 40)
            float x0 = (cc < 1.0f ? cc : cc - 1.0f) * 32.0f;
            float y0 = (r  < 1.0f ? r  : r  - 1.0f) * 32.0f;
            float x1 = (cc < 1.0f ? cc + 2.0f : cc + 1.0f) * 32.0f;
            float y1 = (r + 2.0f) * 32.0f;
            ((float4*)out)[b * KK + i] = make_float4(x0, y0, x1, y1);
        }
    }
}

// ---------------------------------------------------------------------------
extern "C" void kernel_launch(void* const* d_in, const int* in_sizes, int n_in,
                              void* d_out, int out_size) {
    const float* wa = (const float*)d_in[2];   // weight_attn (64,23,40) -> (64,920)
    float* out = (float*)d_out;                // (64,32,4) float32

    prep_kernel<<<ZB + 2, 1024>>>(wa);
    ftopk_kernel<<<dim3(NSMP / 8, BB / 2), 256>>>(wa);
    final_kernel<<<BB, 256>>>(wa, out);
}

// round 8
// speedup vs baseline: 1.3175x; 1.3175x over previous
#include <cuda_runtime.h>
#include <cstdint>

// Problem constants
#define BB   64
#define DD   920
#define NSMP 920
#define KK   32
#define TOT  (BB * NSMP * DD)   // 54,169,600
#define HALF (TOT / 2)          // 27,084,800

// Histogram: 2 x u16 counts packed per u32 (max count 920 < 65536, no carry)
#define CNT_WORDS (BB * KK * DD / 2)   // 942,080 u32 = 3.77 MB
__device__ unsigned g_cnt[CNT_WORDS];
__device__ float    g_thr[BB];

// ---------------------------------------------------------------------------
// threefry2x32 (JAX-exact), both outputs returned
// ---------------------------------------------------------------------------
__device__ __forceinline__ unsigned rotl32(unsigned x, int r) {
    return __funnelshift_l(x, x, r);
}

__device__ __forceinline__ uint2 threefry(unsigned c0, unsigned c1) {
    const unsigned ks0 = 0u, ks1 = 1u, ks2 = 0x1BD11BDAu ^ 0u ^ 1u;
    unsigned x0 = c0 + ks0;
    unsigned x1 = c1 + ks1;
#define RND(r) { x0 += x1; x1 = rotl32(x1, r); x1 ^= x0; }
    RND(13) RND(15) RND(26) RND(6)   x0 += ks1; x1 += ks2 + 1u;
    RND(17) RND(29) RND(16) RND(24)  x0 += ks2; x1 += ks0 + 2u;
    RND(13) RND(15) RND(26) RND(6)   x0 += ks0; x1 += ks1 + 3u;
    RND(17) RND(29) RND(16) RND(24)  x0 += ks1; x1 += ks2 + 4u;
    RND(13) RND(15) RND(26) RND(6)   x0 += ks2; x1 += ks0 + 5u;
#undef RND
    return make_uint2(x0, x1);
}

// bits -> float normal (JAX float32 path; Giles erfinv as in XLA)
__device__ __forceinline__ float bits_to_normal(unsigned b) {
    const float LO = -0.99999994f;  // nextafterf(-1,0)
    float f = __uint_as_float((b >> 9) | 0x3f800000u) - 1.0f;
    float u = fmaxf(LO, f * 2.0f + LO);
    float x2 = u * u;
    float w = -__logf(1.0f - x2);
    float p;
    if (w < 5.0f) {
        w -= 2.5f;
        p = 2.81022636e-08f;
        p = fmaf(p, w, 3.43273939e-07f);
        p = fmaf(p, w, -3.5233877e-06f);
        p = fmaf(p, w, -4.39150654e-06f);
        p = fmaf(p, w, 0.00021858087f);
        p = fmaf(p, w, -0.00125372503f);
        p = fmaf(p, w, -0.00417768164f);
        p = fmaf(p, w, 0.246640727f);
        p = fmaf(p, w, 1.50140941f);
    } else {
        w = sqrtf(w) - 3.0f;
        p = -0.000200214257f;
        p = fmaf(p, w, 0.000100950558f);
        p = fmaf(p, w, 0.00134934322f);
        p = fmaf(p, w, -0.00367342844f);
        p = fmaf(p, w, 0.00573950773f);
        p = fmaf(p, w, -0.0076224613f);
        p = fmaf(p, w, 0.00943887047f);
        p = fmaf(p, w, 1.00167406f);
        p = fmaf(p, w, 2.83297682f);
    }
    return 1.41421356f * (p * u);
}

// ---------------------------------------------------------------------------
// Prep: zero histogram (int4, blocks [0, ZB4)) + per-b thresholds (8 blocks,
// one warp per b). blockDim = 256 everywhere -> no serialized mega-block tail.
// ---------------------------------------------------------------------------
#define ZVEC (CNT_WORDS / 4)          // 235,520 int4 stores
#define ZB4  (ZVEC / 256)             // 920 blocks (exact)

__global__ void __launch_bounds__(256) prep_kernel(const float* __restrict__ wa) {
    if (blockIdx.x < ZB4) {
        int i = blockIdx.x * 256 + threadIdx.x;
        reinterpret_cast<int4*>(g_cnt)[i] = make_int4(0, 0, 0, 0);
        return;
    }
    int gw = (blockIdx.x - ZB4) * 8 + (threadIdx.x >> 5);
    int lane = threadIdx.x & 31;
    if (gw >= BB) return;
    const float* row = wa + gw * DD;
    float v[29];
#pragma unroll
    for (int s = 0; s < 29; s++) {
        int d = s * 32 + lane;
        v[s] = (d < DD) ? row[d] : -1e30f;
    }
    float tl = -1.0f, th = 2.0f;
    for (int it = 0; it < 28; it++) {
        float t = 0.5f * (tl + th);
        int lc = 0;
#pragma unroll
        for (int s = 0; s < 29; s++) lc += (v[s] > t) ? 1 : 0;
        int c = __reduce_add_sync(0xffffffffu, lc);
        if (c > 45) tl = t; else th = t;
    }
    if (lane == 0) g_thr[gw] = 0.5f * (tl + th);
}

// ---------------------------------------------------------------------------
// Per-row top-32 pipeline: threshold search, compact, 64-wide bitonic sort,
// rank by index, packed-u16 atomic histogram update.
// ---------------------------------------------------------------------------
__device__ __forceinline__ void process_row(float (&v)[29], int b, int lane,
                                            unsigned long long* key) {
    float t = g_thr[b];
    float tl = -8.0f, th = 8.0f;
    int c = 0;
    for (int it = 0; it < 60; it++) {
        int lc = 0;
#pragma unroll
        for (int s = 0; s < 29; s++) lc += (v[s] > t) ? 1 : 0;
        c = __reduce_add_sync(0xffffffffu, lc);
        if (c >= 32 && c <= 64) break;
        if (c < 32) th = t; else tl = t;
        t = 0.5f * (tl + th);
    }

    // compact candidates as (ordered_float << 10) | (1023 - d)
    int base = 0;
#pragma unroll
    for (int s = 0; s < 29; s++) {
        bool p = v[s] > t;
        unsigned bal = __ballot_sync(0xffffffffu, p);
        if (p) {
            int pos = base + __popc(bal & ((1u << lane) - 1u));
            if (pos < 64) {
                int d = s * 32 + lane;
                unsigned ub = __float_as_uint(v[s]);
                ub = (ub & 0x80000000u) ? ~ub : (ub | 0x80000000u);
                key[pos] = (((unsigned long long)ub) << 10) |
                           (unsigned long long)(1023 - d);
            }
        }
        base += __popc(bal);
    }
    __syncwarp();

    unsigned long long v0 = (lane < c) ? key[lane] : 0ull;
    unsigned long long v1 = (lane + 32 < c) ? key[lane + 32] : 0ull;

    // bitonic sort, descending, over 64 elements (pos = r*32 + lane)
#pragma unroll
    for (int k = 2; k <= 64; k <<= 1) {
#pragma unroll
        for (int j = k >> 1; j > 0; j >>= 1) {
            if (j == 32) {  // pair (lane, 32+lane), keep max low
                unsigned long long mx = v0 > v1 ? v0 : v1;
                unsigned long long mn = v0 > v1 ? v1 : v0;
                v0 = mx; v1 = mn;
            } else {
                {
                    unsigned long long o = __shfl_xor_sync(0xffffffffu, v0, j);
                    bool km = ((lane & k) == 0);
                    bool lo2 = ((lane & j) == 0);
                    v0 = (km == lo2) ? (v0 > o ? v0 : o) : (v0 < o ? v0 : o);
                }
                {
                    unsigned long long o = __shfl_xor_sync(0xffffffffu, v1, j);
                    int p2 = 32 + lane;
                    bool km = ((p2 & k) == 0);
                    bool lo2 = ((lane & j) == 0);
                    v1 = (km == lo2) ? (v1 > o ? v1 : o) : (v1 < o ? v1 : o);
                }
            }
        }
    }

    // top-32 in v0; recover index, sort ascending; lane == rank after sort
    int d = 1023 - (int)(v0 & 1023ull);
#pragma unroll
    for (int k = 2; k <= 32; k <<= 1) {
#pragma unroll
        for (int j = k >> 1; j > 0; j >>= 1) {
            int o = __shfl_xor_sync(0xffffffffu, d, j);
            bool up = ((lane & k) == 0);
            bool lo2 = ((lane & j) == 0);
            d = (up == lo2) ? (d < o ? d : o) : (d > o ? d : o);
        }
    }
    // packed u16 counter: word = (row_base + d) / 2, halfword selected by d&1
    int idx = (b * KK + lane) * DD + d;           // row_base even (DD even)
    atomicAdd(&g_cnt[idx >> 1], 1u << ((d & 1) << 4));
}

// ---------------------------------------------------------------------------
// Fused kernel, split-warp exchange: CTA = 4 row-pairs (b,n)/(b+32,n), 8 warps.
// Warps 0-3 generate slices 0..14 of pair w (keep row-A vals, export row-B);
// warps 4-7 generate slices 15..28 (keep row-B, export row-A). One sync, each
// warp completes its 29-slice register row and runs the pipeline ONCE.
// Zero noise DRAM traffic; one row per warp -> no register blowup.
// ---------------------------------------------------------------------------
__global__ void __launch_bounds__(256, 5) ftopk_kernel(const float* __restrict__ wa) {
    __shared__ float s_waA[DD];
    __shared__ float s_waB[DD];
    __shared__ float ex_B[4][15][32];   // row-B values, slices 0..14
    __shared__ float ex_A[4][14][32];   // row-A values, slices 15..28
    __shared__ unsigned long long s_key[8][64];

    int b = blockIdx.y;                 // 0..31 (pair: b and b+32)
    int warpid = threadIdx.x >> 5;
    int lane = threadIdx.x & 31;
    int wp = warpid & 3;
    bool isB = warpid >= 4;

    for (int i = threadIdx.x; i < DD; i += 256) {
        s_waA[i] = wa[b * DD + i];
        s_waB[i] = wa[(b + 32) * DD + i];
    }
    __syncthreads();

    int n = blockIdx.x * 4 + wp;        // gridDim.x = 230 -> n in [0,920)
    unsigned rowbase = (unsigned)((b * NSMP + n) * DD);  // < HALF (b < 32)

    float v[29];
    if (!isB) {
        // generate slices 0..14: keep A, export B
#pragma unroll
        for (int s = 0; s < 15; s++) {
            int d = s * 32 + lane;
            unsigned i = rowbase + (unsigned)d;
            uint2 r = threefry(i, i + (unsigned)HALF);
            v[s] = s_waA[d] + 0.1f * bits_to_normal(r.x);
            ex_B[wp][s][lane] = s_waB[d] + 0.1f * bits_to_normal(r.y);
        }
    } else {
        // generate slices 15..28: keep B, export A
#pragma unroll
        for (int s = 15; s < 29; s++) {
            int d = s * 32 + lane;
            if (d < DD) {
                unsigned i = rowbase + (unsigned)d;
                uint2 r = threefry(i, i + (unsigned)HALF);
                v[s] = s_waB[d] + 0.1f * bits_to_normal(r.y);
                ex_A[wp][s - 15][lane] = s_waA[d] + 0.1f * bits_to_normal(r.x);
            } else {
                v[s] = -3.0e38f;
                ex_A[wp][s - 15][lane] = -3.0e38f;
            }
        }
    }
    __syncthreads();

    if (!isB) {
#pragma unroll
        for (int s = 15; s < 29; s++) v[s] = ex_A[wp][s - 15][lane];
    } else {
#pragma unroll
        for (int s = 0; s < 15; s++) v[s] = ex_B[wp][s][lane];
    }

    process_row(v, isB ? b + 32 : b, lane, s_key[warpid]);
}

// ---------------------------------------------------------------------------
// Final: s = (cnt . wa) / 920, then bbox -> out (b, k, 4)
// ---------------------------------------------------------------------------
__global__ void final_kernel(const float* __restrict__ wa, float* __restrict__ out) {
    __shared__ float s_wa[DD];
    int b = blockIdx.x;
    int warpid = threadIdx.x >> 5;
    int lane = threadIdx.x & 31;
    for (int i = threadIdx.x; i < DD; i += 256) s_wa[i] = wa[b * DD + i];
    __syncthreads();
    for (int i = warpid; i < KK; i += 8) {
        int rowbase = (b * KK + i) * DD;           // even
        float acc = 0.0f;
        for (int d = lane; d < DD; d += 32) {
            unsigned w = g_cnt[(rowbase + d) >> 1];
            unsigned cnt = (w >> ((d & 1) << 4)) & 0xffffu;
            acc += (float)cnt * s_wa[d];
        }
#pragma unroll
        for (int o = 16; o; o >>= 1) acc += __shfl_xor_sync(0xffffffffu, acc, o);
        if (lane == 0) {
            float sv = acc / 920.0f;
            float r  = floorf(sv / 40.0f);
            float cc = sv - 40.0f * r;             // jnp.mod(sv, 40)
            float x0 = (cc < 1.0f ? cc : cc - 1.0f) * 32.0f;
            float y0 = (r  < 1.0f ? r  : r  - 1.0f) * 32.0f;
            float x1 = (cc < 1.0f ? cc + 2.0f : cc + 1.0f) * 32.0f;
            float y1 = (r + 2.0f) * 32.0f;
            ((float4*)out)[b * KK + i] = make_float4(x0, y0, x1, y1);
        }
    }
}

// ---------------------------------------------------------------------------
extern "C" void kernel_launch(void* const* d_in, const int* in_sizes, int n_in,
                              void* d_out, int out_size) {
    const float* wa = (const float*)d_in[2];   // weight_attn (64,23,40) -> (64,920)
    float* out = (float*)d_out;                // (64,32,4) float32

    prep_kernel<<<ZB4 + 8, 256>>>(wa);
    ftopk_kernel<<<dim3(NSMP / 4, BB / 2), 256>>>(wa);
    final_kernel<<<BB, 256>>>(wa, out);
}

// round 9
// speedup vs baseline: 1.9437x; 1.4753x over previous
#include <cuda_runtime.h>
#include <cstdint>

// Problem constants
#define BB   64
#define DD   920
#define NSMP 920
#define KK   32
#define TOT  (BB * NSMP * DD)   // 54,169,600
#define HALF (TOT / 2)          // 27,084,800

// Fixed-point accumulator for s[b,k]: sum of round(wa*2^22), <= 920*2^22 < 2^32.
// Integer atomics are order-independent -> deterministic output.
__device__ unsigned g_s[BB * KK];     // 8 KB

#define QSCALE 4194304.0f             // 2^22

// ---------------------------------------------------------------------------
// threefry2x32 (JAX-exact), both outputs returned
// ---------------------------------------------------------------------------
__device__ __forceinline__ unsigned rotl32(unsigned x, int r) {
    return __funnelshift_l(x, x, r);
}

__device__ __forceinline__ uint2 threefry(unsigned c0, unsigned c1) {
    const unsigned ks0 = 0u, ks1 = 1u, ks2 = 0x1BD11BDAu ^ 0u ^ 1u;
    unsigned x0 = c0 + ks0;
    unsigned x1 = c1 + ks1;
#define RND(r) { x0 += x1; x1 = rotl32(x1, r); x1 ^= x0; }
    RND(13) RND(15) RND(26) RND(6)   x0 += ks1; x1 += ks2 + 1u;
    RND(17) RND(29) RND(16) RND(24)  x0 += ks2; x1 += ks0 + 2u;
    RND(13) RND(15) RND(26) RND(6)   x0 += ks0; x1 += ks1 + 3u;
    RND(17) RND(29) RND(16) RND(24)  x0 += ks1; x1 += ks2 + 4u;
    RND(13) RND(15) RND(26) RND(6)   x0 += ks2; x1 += ks0 + 5u;
#undef RND
    return make_uint2(x0, x1);
}

// bits -> float normal (JAX float32 path; Giles erfinv as in XLA)
__device__ __forceinline__ float bits_to_normal(unsigned b) {
    const float LO = -0.99999994f;  // nextafterf(-1,0)
    float f = __uint_as_float((b >> 9) | 0x3f800000u) - 1.0f;
    float u = fmaxf(LO, f * 2.0f + LO);
    float x2 = u * u;
    float w = -__logf(1.0f - x2);
    float p;
    if (w < 5.0f) {
        w -= 2.5f;
        p = 2.81022636e-08f;
        p = fmaf(p, w, 3.43273939e-07f);
        p = fmaf(p, w, -3.5233877e-06f);
        p = fmaf(p, w, -4.39150654e-06f);
        p = fmaf(p, w, 0.00021858087f);
        p = fmaf(p, w, -0.00125372503f);
        p = fmaf(p, w, -0.00417768164f);
        p = fmaf(p, w, 0.246640727f);
        p = fmaf(p, w, 1.50140941f);
    } else {
        w = sqrtf(w) - 3.0f;
        p = -0.000200214257f;
        p = fmaf(p, w, 0.000100950558f);
        p = fmaf(p, w, 0.00134934322f);
        p = fmaf(p, w, -0.00367342844f);
        p = fmaf(p, w, 0.00573950773f);
        p = fmaf(p, w, -0.0076224613f);
        p = fmaf(p, w, 0.00943887047f);
        p = fmaf(p, w, 1.00167406f);
        p = fmaf(p, w, 2.83297682f);
    }
    return 1.41421356f * (p * u);
}

// ---------------------------------------------------------------------------
// Zero the 2048-word accumulator (single tiny block)
// ---------------------------------------------------------------------------
__global__ void zero_kernel() {
    reinterpret_cast<int4*>(g_s)[threadIdx.x] = make_int4(0, 0, 0, 0);  // 512 thr
}

// ---------------------------------------------------------------------------
// Fused kernel.  CTA = 4 row-pairs (b,n)/(b+32,n), 8 warps, 256 threads.
// The threefry pairing (j, j+HALF) couples rows b and b+32 at equal (n,d):
// warps 0-3 generate slices 0..14 for pair wp (keep row-A, export row-B via
// smem), warps 4-7 generate slices 15..28 (keep row-B, export row-A).
// Selection (no sort): window-bisect count into [32,64] on the 29-reg row,
// ballot-compact (index-ordered!) into 64 (val,idx) smem slots, bisect the
// 2-reg slot view to exactly 32, then rank = kept-prefix-count by position.
// Emit: integer atomicAdd of round(wa[d]*2^22) into s[b, rank].
// ---------------------------------------------------------------------------
__global__ void __launch_bounds__(256) ftopk_kernel(const float* __restrict__ wa) {
    __shared__ float s_waA[DD];
    __shared__ float s_waB[DD];
    __shared__ float ex_B[4][15][32];   // row-B values, slices 0..14
    __shared__ float ex_A[4][14][32];   // row-A values, slices 15..28
    __shared__ float s_val[8][64];
    __shared__ unsigned short s_idx[8][64];

    int b = blockIdx.y;                 // 0..31 (pair: b and b+32)
    int warpid = threadIdx.x >> 5;
    int lane = threadIdx.x & 31;
    int wp = warpid & 3;
    bool isB = warpid >= 4;

    for (int i = threadIdx.x; i < DD; i += 256) {
        s_waA[i] = wa[b * DD + i];
        s_waB[i] = wa[(b + 32) * DD + i];
    }
    __syncthreads();

    int n = blockIdx.x * 4 + wp;        // gridDim.x = 230 -> n in [0,920)
    unsigned rowbase = (unsigned)((b * NSMP + n) * DD);  // < HALF (b < 32)

    float v[29];
    if (!isB) {
#pragma unroll
        for (int s = 0; s < 15; s++) {
            int d = s * 32 + lane;
            unsigned i = rowbase + (unsigned)d;
            uint2 r = threefry(i, i + (unsigned)HALF);
            v[s] = s_waA[d] + 0.1f * bits_to_normal(r.x);
            ex_B[wp][s][lane] = s_waB[d] + 0.1f * bits_to_normal(r.y);
        }
    } else {
#pragma unroll
        for (int s = 15; s < 29; s++) {
            int d = s * 32 + lane;
            if (d < DD) {
                unsigned i = rowbase + (unsigned)d;
                uint2 r = threefry(i, i + (unsigned)HALF);
                v[s] = s_waB[d] + 0.1f * bits_to_normal(r.y);
                ex_A[wp][s - 15][lane] = s_waA[d] + 0.1f * bits_to_normal(r.x);
            } else {
                v[s] = -3.0e38f;
                ex_A[wp][s - 15][lane] = -3.0e38f;
            }
        }
    }
    __syncthreads();

    if (!isB) {
#pragma unroll
        for (int s = 15; s < 29; s++) v[s] = ex_A[wp][s - 15][lane];
    } else {
#pragma unroll
        for (int s = 0; s < 15; s++) v[s] = ex_B[wp][s][lane];
    }

    // ---- window bisection: count(v > t) into [32, 64] ----
    float tl = -0.25f, th = 2.0f, t = 0.875f;
    int c = 0;
    for (int it = 0; it < 40; it++) {
        int lc = 0;
#pragma unroll
        for (int s = 0; s < 29; s++) lc += (v[s] > t) ? 1 : 0;
        c = __reduce_add_sync(0xffffffffu, lc);
        if (c >= 32 && c <= 64) break;
        if (c < 32) th = t; else tl = t;
        t = 0.5f * (tl + th);
    }

    // ---- compact candidates (index-ordered) into (val, idx) slots ----
    int base = 0;
#pragma unroll
    for (int s = 0; s < 29; s++) {
        bool p = v[s] > t;
        unsigned bal = __ballot_sync(0xffffffffu, p);
        if (p) {
            int pos = base + __popc(bal & ((1u << lane) - 1u));
            if (pos < 64) {
                s_val[warpid][pos] = v[s];
                s_idx[warpid][pos] = (unsigned short)(s * 32 + lane);
            }
        }
        base += __popc(bal);
    }
    __syncwarp();

    float s0 = (lane < c)      ? s_val[warpid][lane]      : -3.0e38f;
    float s1 = (lane + 32 < c) ? s_val[warpid][lane + 32] : -3.0e38f;

    // ---- inner bisection on the 64 slots: isolate exactly 32 ----
    if (c != 32) {
        float til = t, tih = 2.0f;   // count(>til) = c >= 32 ; count(>2.0) = 0
        for (int it = 0; it < 32; it++) {
            float tm = 0.5f * (til + tih);
            int lc = ((s0 > tm) ? 1 : 0) + ((s1 > tm) ? 1 : 0);
            int cc = __reduce_add_sync(0xffffffffu, lc);
            if (cc >= 32) til = tm; else tih = tm;
            if (cc == 32) break;
        }
        t = til;                     // exact-32 threshold (ties: prob ~0, trimmed)
    }

    // ---- rank = prefix count of kept slots in position (= index) order ----
    bool k0 = s0 > t;
    bool k1 = s1 > t;
    unsigned keep0 = __ballot_sync(0xffffffffu, k0);
    unsigned keep1 = __ballot_sync(0xffffffffu, k1);
    unsigned below = (1u << lane) - 1u;
    int myb = isB ? b + 32 : b;
    const float* myrow = isB ? s_waB : s_waA;

    if (k0) {
        int r = __popc(keep0 & below);
        if (r < KK) {
            int d = (int)s_idx[warpid][lane];
            unsigned q = __float2uint_rn(myrow[d] * QSCALE);
            atomicAdd(&g_s[myb * KK + r], q);
        }
    }
    if (k1) {
        int r = __popc(keep0) + __popc(keep1 & below);
        if (r < KK) {
            int d = (int)s_idx[warpid][lane + 32];
            unsigned q = __float2uint_rn(myrow[d] * QSCALE);
            atomicAdd(&g_s[myb * KK + r], q);
        }
    }
}

// ---------------------------------------------------------------------------
// Final: s = g_s / (2^22 * 920), then bbox -> out (b, k, 4)
// ---------------------------------------------------------------------------
__global__ void final_kernel(float* __restrict__ out) {
    int idx = blockIdx.x * 1024 + threadIdx.x;   // 0..2047
    if (idx >= BB * KK) return;
    float sv = __uint2float_rn(g_s[idx]) * (1.0f / (QSCALE * 920.0f));
    float r  = floorf(sv / 40.0f);
    float cc = sv - 40.0f * r;                   // jnp.mod(sv, 40)
    float x0 = (cc < 1.0f ? cc : cc - 1.0f) * 32.0f;
    float y0 = (r  < 1.0f ? r  : r  - 1.0f) * 32.0f;
    float x1 = (cc < 1.0f ? cc + 2.0f : cc + 1.0f) * 32.0f;
    float y1 = (r + 2.0f) * 32.0f;
    ((float4*)out)[idx] = make_float4(x0, y0, x1, y1);
}

// ---------------------------------------------------------------------------
extern "C" void kernel_launch(void* const* d_in, const int* in_sizes, int n_in,
                              void* d_out, int out_size) {
    const float* wa = (const float*)d_in[2];   // weight_attn (64,23,40) -> (64,920)
    float* out = (float*)d_out;                // (64,32,4) float32

    zero_kernel<<<1, 512>>>();
    ftopk_kernel<<<dim3(NSMP / 4, BB / 2), 256>>>(wa);
    final_kernel<<<2, 1024>>>(out);
}

// round 10
// speedup vs baseline: 2.4981x; 1.2852x over previous
#include <cuda_runtime.h>
#include <cstdint>

// Problem constants
#define BB   64
#define DD   920
#define NSMP 920
#define KK   32
#define TOT  (BB * NSMP * DD)   // 54,169,600
#define HALF (TOT / 2)          // 27,084,800

// Fixed-point accumulator for s[b,k]: sum of round(wa*2^22), <= 920*2^22 < 2^32.
// Zero-initialized at module load; final_kernel restores it to zero after each
// consumption, so every kernel_launch (and every graph replay) starts from 0.
__device__ unsigned g_s[BB * KK];     // 8 KB

#define QSCALE 4194304.0f             // 2^22

// ---------------------------------------------------------------------------
// threefry2x32 (JAX-exact), both outputs returned
// ---------------------------------------------------------------------------
__device__ __forceinline__ unsigned rotl32(unsigned x, int r) {
    return __funnelshift_l(x, x, r);
}

__device__ __forceinline__ uint2 threefry(unsigned c0, unsigned c1) {
    const unsigned ks0 = 0u, ks1 = 1u, ks2 = 0x1BD11BDAu ^ 0u ^ 1u;
    unsigned x0 = c0 + ks0;
    unsigned x1 = c1 + ks1;
#define RND(r) { x0 += x1; x1 = rotl32(x1, r); x1 ^= x0; }
    RND(13) RND(15) RND(26) RND(6)   x0 += ks1; x1 += ks2 + 1u;
    RND(17) RND(29) RND(16) RND(24)  x0 += ks2; x1 += ks0 + 2u;
    RND(13) RND(15) RND(26) RND(6)   x0 += ks0; x1 += ks1 + 3u;
    RND(17) RND(29) RND(16) RND(24)  x0 += ks1; x1 += ks2 + 4u;
    RND(13) RND(15) RND(26) RND(6)   x0 += ks2; x1 += ks0 + 5u;
#undef RND
    return make_uint2(x0, x1);
}

// ---------------------------------------------------------------------------
// Packed f32x2 helpers (Blackwell): per-half IEEE rn -> bit-identical to the
// scalar fmaf/fmul chain, at half the fma-pipe instruction count.
// ---------------------------------------------------------------------------
__device__ __forceinline__ unsigned long long pk2(float lo, float hi) {
    unsigned long long r;
    asm("mov.b64 %0, {%1, %2};" : "=l"(r) : "f"(lo), "f"(hi));
    return r;
}
__device__ __forceinline__ void upk2(unsigned long long v, float& lo, float& hi) {
    asm("mov.b64 {%0, %1}, %2;" : "=f"(lo), "=f"(hi) : "l"(v));
}
__device__ __forceinline__ unsigned long long fma2_(unsigned long long a,
                                                    unsigned long long b,
                                                    unsigned long long c) {
    unsigned long long r;
    asm("fma.rn.f32x2 %0, %1, %2, %3;" : "=l"(r) : "l"(a), "l"(b), "l"(c));
    return r;
}
__device__ __forceinline__ unsigned long long mul2_(unsigned long long a,
                                                    unsigned long long b) {
    unsigned long long r;
    asm("mul.rn.f32x2 %0, %1, %2;" : "=l"(r) : "l"(a), "l"(b));
    return r;
}
__device__ __forceinline__ unsigned long long add2_(unsigned long long a,
                                                    unsigned long long b) {
    unsigned long long r;
    asm("add.rn.f32x2 %0, %1, %2;" : "=l"(r) : "l"(a), "l"(b));
    return r;
}

// Scalar fallback (rare w >= 5 halves, ~0.34%/element), identical to the
// original scalar path from the passing kernels.
__device__ __noinline__ float erfinv_tail(float u, float w) {
    float p;
    if (w < 5.0f) {
        w -= 2.5f;
        p = 2.81022636e-08f;
        p = fmaf(p, w, 3.43273939e-07f);
        p = fmaf(p, w, -3.5233877e-06f);
        p = fmaf(p, w, -4.39150654e-06f);
        p = fmaf(p, w, 0.00021858087f);
        p = fmaf(p, w, -0.00125372503f);
        p = fmaf(p, w, -0.00417768164f);
        p = fmaf(p, w, 0.246640727f);
        p = fmaf(p, w, 1.50140941f);
    } else {
        w = sqrtf(w) - 3.0f;
        p = -0.000200214257f;
        p = fmaf(p, w, 0.000100950558f);
        p = fmaf(p, w, 0.00134934322f);
        p = fmaf(p, w, -0.00367342844f);
        p = fmaf(p, w, 0.00573950773f);
        p = fmaf(p, w, -0.0076224613f);
        p = fmaf(p, w, 0.00943887047f);
        p = fmaf(p, w, 1.00167406f);
        p = fmaf(p, w, 2.83297682f);
    }
    return 1.41421356f * (p * u);
}

// Two normals from one threefry output pair, Giles polynomial evaluated in
// packed f32x2 on the common (w<5) branch.  Bit-identical to the scalar code.
__device__ __forceinline__ void normals2(unsigned b0, unsigned b1,
                                         float& n0, float& n1) {
    const float LO = -0.99999994f;  // nextafterf(-1,0)
    float f0 = __uint_as_float((b0 >> 9) | 0x3f800000u) - 1.0f;
    float f1 = __uint_as_float((b1 >> 9) | 0x3f800000u) - 1.0f;
    float u0 = fmaxf(LO, f0 * 2.0f + LO);
    float u1 = fmaxf(LO, f1 * 2.0f + LO);
    unsigned long long u  = pk2(u0, u1);
    unsigned long long x2 = mul2_(u, u);
    // 1 - x2 via fma(x2,-1,1): exact same rounding as the FSUB
    unsigned long long om = fma2_(x2, pk2(-1.0f, -1.0f), pk2(1.0f, 1.0f));
    float o0, o1;
    upk2(om, o0, o1);
    float w0 = -__logf(o0);
    float w1 = -__logf(o1);
    if (__builtin_expect(w0 < 5.0f && w1 < 5.0f, 1)) {
        unsigned long long w = add2_(pk2(w0, w1), pk2(-2.5f, -2.5f));
        unsigned long long p = pk2(2.81022636e-08f, 2.81022636e-08f);
        p = fma2_(p, w, pk2(3.43273939e-07f, 3.43273939e-07f));
        p = fma2_(p, w, pk2(-3.5233877e-06f, -3.5233877e-06f));
        p = fma2_(p, w, pk2(-4.39150654e-06f, -4.39150654e-06f));
        p = fma2_(p, w, pk2(0.00021858087f, 0.00021858087f));
        p = fma2_(p, w, pk2(-0.00125372503f, -0.00125372503f));
        p = fma2_(p, w, pk2(-0.00417768164f, -0.00417768164f));
        p = fma2_(p, w, pk2(0.246640727f, 0.246640727f));
        p = fma2_(p, w, pk2(1.50140941f, 1.50140941f));
        unsigned long long res =
            mul2_(mul2_(p, u), pk2(1.41421356f, 1.41421356f));
        upk2(res, n0, n1);
    } else {
        n0 = erfinv_tail(u0, w0);
        n1 = erfinv_tail(u1, w1);
    }
}

// ---------------------------------------------------------------------------
// Per-row top-32 pipeline: staged threshold search (wa ~ U(0,1) -> start at
// t=1.0, narrow bracket; wide-bracket fallback for safety), index-ordered
// ballot compaction, exact-32 inner bisection, rank-by-position, and a
// fixed-point integer atomic accumulate of wa[d] into s[b, rank].
// ---------------------------------------------------------------------------
__device__ __forceinline__ void process_row(float (&v)[29], int b, int lane,
                                            int warpid, const float* myrow,
                                            float (*s_val)[64],
                                            unsigned short (*s_idx)[64]) {
    float t = 1.0f;
    int c = 0;
    {
        float tl = 0.85f, th = 1.15f;
        for (int it = 0; it < 8; it++) {
            int lc = 0;
#pragma unroll
            for (int s = 0; s < 29; s++) lc += (v[s] > t) ? 1 : 0;
            c = __reduce_add_sync(0xffffffffu, lc);
            if (c >= 32 && c <= 64) break;
            if (c < 32) th = t; else tl = t;
            t = 0.5f * (tl + th);
        }
    }
    if (c < 32 || c > 64) {   // essentially never taken; guarantees the window
        float tl = -8.0f, th = 8.0f;
        t = 0.0f;
        for (int it = 0; it < 60; it++) {
            int lc = 0;
#pragma unroll
            for (int s = 0; s < 29; s++) lc += (v[s] > t) ? 1 : 0;
            c = __reduce_add_sync(0xffffffffu, lc);
            if (c >= 32 && c <= 64) break;
            if (c < 32) th = t; else tl = t;
            t = 0.5f * (tl + th);
        }
    }

    // compact candidates (index-ordered) into (val, idx) slots
    int base = 0;
#pragma unroll
    for (int s = 0; s < 29; s++) {
        bool p = v[s] > t;
        unsigned bal = __ballot_sync(0xffffffffu, p);
        if (p) {
            int pos = base + __popc(bal & ((1u << lane) - 1u));
            if (pos < 64) {
                s_val[warpid][pos] = v[s];
                s_idx[warpid][pos] = (unsigned short)(s * 32 + lane);
            }
        }
        base += __popc(bal);
    }
    __syncwarp();

    float s0 = (lane < c)      ? s_val[warpid][lane]      : -3.0e38f;
    float s1 = (lane + 32 < c) ? s_val[warpid][lane + 32] : -3.0e38f;

    // inner bisection on the <=64 slots: isolate exactly 32
    if (c != 32) {
        float til = t, tih = 2.0f;   // count(>til) = c >= 32 ; count(>2.0) = 0
        for (int it = 0; it < 32; it++) {
            float tm = 0.5f * (til + tih);
            int lc = ((s0 > tm) ? 1 : 0) + ((s1 > tm) ? 1 : 0);
            int cc = __reduce_add_sync(0xffffffffu, lc);
            if (cc >= 32) til = tm; else tih = tm;
            if (cc == 32) break;
        }
        t = til;
    }

    // rank = prefix count of kept slots in position (= index) order
    bool k0 = s0 > t;
    bool k1 = s1 > t;
    unsigned keep0 = __ballot_sync(0xffffffffu, k0);
    unsigned keep1 = __ballot_sync(0xffffffffu, k1);
    unsigned below = (1u << lane) - 1u;

    if (k0) {
        int r = __popc(keep0 & below);
        if (r < KK) {
            int d = (int)s_idx[warpid][lane];
            unsigned q = __float2uint_rn(myrow[d] * QSCALE);
            atomicAdd(&g_s[b * KK + r], q);
        }
    }
    if (k1) {
        int r = __popc(keep0) + __popc(keep1 & below);
        if (r < KK) {
            int d = (int)s_idx[warpid][lane + 32];
            unsigned q = __float2uint_rn(myrow[d] * QSCALE);
            atomicAdd(&g_s[b * KK + r], q);
        }
    }
}

// ---------------------------------------------------------------------------
// Fused kernel.  CTA = 4 row-pairs (b,n)/(b+32,n), 8 warps.  The threefry
// pairing (j, j+HALF) couples rows b and b+32 at equal (n,d): warps 0-3
// generate slices 0..14 for pair wp (keep row-A, export row-B via smem),
// warps 4-7 generate slices 15..28 (keep row-B, export row-A).  One sync,
// each warp completes its 29-slice register row and runs the pipeline once.
// ---------------------------------------------------------------------------
__global__ void __launch_bounds__(256) ftopk_kernel(const float* __restrict__ wa) {
    __shared__ float s_waA[DD];
    __shared__ float s_waB[DD];
    __shared__ float ex_B[4][15][32];   // row-B values, slices 0..14
    __shared__ float ex_A[4][14][32];   // row-A values, slices 15..28
    __shared__ float s_val[8][64];
    __shared__ unsigned short s_idx[8][64];

    int b = blockIdx.y;                 // 0..31 (pair: b and b+32)
    int warpid = threadIdx.x >> 5;
    int lane = threadIdx.x & 31;
    int wp = warpid & 3;
    bool isB = warpid >= 4;

    for (int i = threadIdx.x; i < DD; i += 256) {
        s_waA[i] = wa[b * DD + i];
        s_waB[i] = wa[(b + 32) * DD + i];
    }
    __syncthreads();

    int n = blockIdx.x * 4 + wp;        // gridDim.x = 230 -> n in [0,920)
    unsigned rowbase = (unsigned)((b * NSMP + n) * DD);  // < HALF (b < 32)

    float v[29];
    if (!isB) {
#pragma unroll
        for (int s = 0; s < 15; s++) {
            int d = s * 32 + lane;
            unsigned i = rowbase + (unsigned)d;
            uint2 r = threefry(i, i + (unsigned)HALF);
            float n0, n1;
            normals2(r.x, r.y, n0, n1);
            v[s] = s_waA[d] + 0.1f * n0;
            ex_B[wp][s][lane] = s_waB[d] + 0.1f * n1;
        }
    } else {
#pragma unroll
        for (int s = 15; s < 29; s++) {
            int d = s * 32 + lane;
            if (d < DD) {
                unsigned i = rowbase + (unsigned)d;
                uint2 r = threefry(i, i + (unsigned)HALF);
                float n0, n1;
                normals2(r.x, r.y, n0, n1);
                v[s] = s_waB[d] + 0.1f * n1;
                ex_A[wp][s - 15][lane] = s_waA[d] + 0.1f * n0;
            } else {
                v[s] = -3.0e38f;
                ex_A[wp][s - 15][lane] = -3.0e38f;
            }
        }
    }
    __syncthreads();

    if (!isB) {
#pragma unroll
        for (int s = 15; s < 29; s++) v[s] = ex_A[wp][s - 15][lane];
    } else {
#pragma unroll
        for (int s = 0; s < 15; s++) v[s] = ex_B[wp][s][lane];
    }

    process_row(v, isB ? b + 32 : b, lane, warpid, isB ? s_waB : s_waA,
                s_val, s_idx);
}

// ---------------------------------------------------------------------------
// Final: s = g_s / (2^22 * 920), bbox -> out; then restore g_s to zero so the
// next kernel_launch / graph replay starts from a clean accumulator.
// ---------------------------------------------------------------------------
__global__ void final_kernel(float* __restrict__ out) {
    int idx = blockIdx.x * 1024 + threadIdx.x;   // 0..2047
    if (idx >= BB * KK) return;
    unsigned acc = g_s[idx];
    g_s[idx] = 0u;                               // re-arm for next launch
    float sv = __uint2float_rn(acc) * (1.0f / (QSCALE * 920.0f));
    float r  = floorf(sv / 40.0f);
    float cc = sv - 40.0f * r;                   // jnp.mod(sv, 40)
    float x0 = (cc < 1.0f ? cc : cc - 1.0f) * 32.0f;
    float y0 = (r  < 1.0f ? r  : r  - 1.0f) * 32.0f;
    float x1 = (cc < 1.0f ? cc + 2.0f : cc + 1.0f) * 32.0f;
    float y1 = (r + 2.0f) * 32.0f;
    ((float4*)out)[idx] = make_float4(x0, y0, x1, y1);
}

// ---------------------------------------------------------------------------
extern "C" void kernel_launch(void* const* d_in, const int* in_sizes, int n_in,
                              void* d_out, int out_size) {
    const float* wa = (const float*)d_in[2];   // weight_attn (64,23,40) -> (64,920)
    float* out = (float*)d_out;                // (64,32,4) float32

    ftopk_kernel<<<dim3(NSMP / 4, BB / 2), 256>>>(wa);
    final_kernel<<<2, 1024>>>(out);
}

// round 11
// speedup vs baseline: 2.5232x; 1.0101x over previous
#include <cuda_runtime.h>
#include <cstdint>

// Problem constants
#define BB   64
#define DD   920
#define NSMP 920
#define KK   32
#define TOT  (BB * NSMP * DD)   // 54,169,600
#define HALF (TOT / 2)          // 27,084,800
#define NCTA ((NSMP / 4) * (BB / 2))   // 7360 CTAs in the fused grid

// Fixed-point accumulator for s[b,k]: sum of round(wa*2^22), <= 920*2^22 < 2^32.
// Zero-initialized at module load; the last-CTA epilogue restores it to zero
// after each consumption, so every launch / graph replay starts from 0.
__device__ unsigned g_s[BB * KK];     // 8 KB
__device__ unsigned g_ticket;         // last-CTA election; re-armed to 0

#define QSCALE 4194304.0f             // 2^22

// ---------------------------------------------------------------------------
// threefry2x32 (JAX-exact), both outputs returned
// ---------------------------------------------------------------------------
__device__ __forceinline__ unsigned rotl32(unsigned x, int r) {
    return __funnelshift_l(x, x, r);
}

__device__ __forceinline__ uint2 threefry(unsigned c0, unsigned c1) {
    const unsigned ks0 = 0u, ks1 = 1u, ks2 = 0x1BD11BDAu ^ 0u ^ 1u;
    unsigned x0 = c0 + ks0;
    unsigned x1 = c1 + ks1;
#define RND(r) { x0 += x1; x1 = rotl32(x1, r); x1 ^= x0; }
    RND(13) RND(15) RND(26) RND(6)   x0 += ks1; x1 += ks2 + 1u;
    RND(17) RND(29) RND(16) RND(24)  x0 += ks2; x1 += ks0 + 2u;
    RND(13) RND(15) RND(26) RND(6)   x0 += ks0; x1 += ks1 + 3u;
    RND(17) RND(29) RND(16) RND(24)  x0 += ks1; x1 += ks2 + 4u;
    RND(13) RND(15) RND(26) RND(6)   x0 += ks2; x1 += ks0 + 5u;
#undef RND
    return make_uint2(x0, x1);
}

// ---------------------------------------------------------------------------
// Packed f32x2 helpers (Blackwell): per-half IEEE rn -> bit-identical to the
// scalar fmaf/fmul chain, at half the fma-pipe instruction count.
// ---------------------------------------------------------------------------
__device__ __forceinline__ unsigned long long pk2(float lo, float hi) {
    unsigned long long r;
    asm("mov.b64 %0, {%1, %2};" : "=l"(r) : "f"(lo), "f"(hi));
    return r;
}
__device__ __forceinline__ void upk2(unsigned long long v, float& lo, float& hi) {
    asm("mov.b64 {%0, %1}, %2;" : "=f"(lo), "=f"(hi) : "l"(v));
}
__device__ __forceinline__ unsigned long long fma2_(unsigned long long a,
                                                    unsigned long long b,
                                                    unsigned long long c) {
    unsigned long long r;
    asm("fma.rn.f32x2 %0, %1, %2, %3;" : "=l"(r) : "l"(a), "l"(b), "l"(c));
    return r;
}
__device__ __forceinline__ unsigned long long mul2_(unsigned long long a,
                                                    unsigned long long b) {
    unsigned long long r;
    asm("mul.rn.f32x2 %0, %1, %2;" : "=l"(r) : "l"(a), "l"(b));
    return r;
}
__device__ __forceinline__ unsigned long long add2_(unsigned long long a,
                                                    unsigned long long b) {
    unsigned long long r;
    asm("add.rn.f32x2 %0, %1, %2;" : "=l"(r) : "l"(a), "l"(b));
    return r;
}

// Rare (w >= 5, ~0.34% per value) tail: identical to the w>=5 branch of the
// original scalar erfinv path -> bit-identical where it is applied.
__device__ __noinline__ float erfinv_tail5(float u, float w) {
    w = sqrtf(w) - 3.0f;
    float p = -0.000200214257f;
    p = fmaf(p, w, 0.000100950558f);
    p = fmaf(p, w, 0.00134934322f);
    p = fmaf(p, w, -0.00367342844f);
    p = fmaf(p, w, 0.00573950773f);
    p = fmaf(p, w, -0.0076224613f);
    p = fmaf(p, w, 0.00943887047f);
    p = fmaf(p, w, 1.00167406f);
    p = fmaf(p, w, 2.83297682f);
    return 1.41421356f * (p * u);
}

// Two normals from one threefry output pair.  Central Giles polynomial is
// evaluated unconditionally in packed f32x2 (per-half rn == scalar fmaf chain);
// rare w>=5 halves are individually overwritten by the tail path.
__device__ __forceinline__ void normals2(unsigned b0, unsigned b1,
                                         float& n0, float& n1) {
    const float LO = -0.99999994f;  // nextafterf(-1,0)
    float f0 = __uint_as_float((b0 >> 9) | 0x3f800000u) - 1.0f;
    float f1 = __uint_as_float((b1 >> 9) | 0x3f800000u) - 1.0f;
    float u0 = fmaxf(LO, f0 * 2.0f + LO);
    float u1 = fmaxf(LO, f1 * 2.0f + LO);
    unsigned long long u  = pk2(u0, u1);
    unsigned long long x2 = mul2_(u, u);
    // 1 - x2 via fma(x2,-1,1): exact same rounding as the FSUB
    unsigned long long om = fma2_(x2, pk2(-1.0f, -1.0f), pk2(1.0f, 1.0f));
    float o0, o1;
    upk2(om, o0, o1);
    float w0 = -__logf(o0);
    float w1 = -__logf(o1);
    unsigned long long w = add2_(pk2(w0, w1), pk2(-2.5f, -2.5f));
    unsigned long long p = pk2(2.81022636e-08f, 2.81022636e-08f);
    p = fma2_(p, w, pk2(3.43273939e-07f, 3.43273939e-07f));
    p = fma2_(p, w, pk2(-3.5233877e-06f, -3.5233877e-06f));
    p = fma2_(p, w, pk2(-4.39150654e-06f, -4.39150654e-06f));
    p = fma2_(p, w, pk2(0.00021858087f, 0.00021858087f));
    p = fma2_(p, w, pk2(-0.00125372503f, -0.00125372503f));
    p = fma2_(p, w, pk2(-0.00417768164f, -0.00417768164f));
    p = fma2_(p, w, pk2(0.246640727f, 0.246640727f));
    p = fma2_(p, w, pk2(1.50140941f, 1.50140941f));
    unsigned long long res = mul2_(mul2_(p, u), pk2(1.41421356f, 1.41421356f));
    upk2(res, n0, n1);
    if (__builtin_expect(w0 >= 5.0f, 0)) n0 = erfinv_tail5(u0, w0);
    if (__builtin_expect(w1 >= 5.0f, 0)) n1 = erfinv_tail5(u1, w1);
}

// ---------------------------------------------------------------------------
// Per-row top-32 pipeline: staged threshold search (wa ~ U(0,1) -> start at
// t=1.0, narrow bracket; wide-bracket fallback for safety), index-ordered
// ballot compaction, exact-32 inner bisection (v < 1.516 -> tih=1.6 is a
// guaranteed upper bound), rank-by-position, and a fixed-point integer
// atomic accumulate of wa[d] into s[b, rank].
// ---------------------------------------------------------------------------
__device__ __forceinline__ void process_row(float (&v)[29], int b, int lane,
                                            int warpid, const float* myrow,
                                            float (*s_val)[64],
                                            unsigned short (*s_idx)[64]) {
    float t = 1.0f;
    int c = 0;
    {
        float tl = 0.85f, th = 1.15f;
        for (int it = 0; it < 8; it++) {
            int lc = 0;
#pragma unroll
            for (int s = 0; s < 29; s++) lc += (v[s] > t) ? 1 : 0;
            c = __reduce_add_sync(0xffffffffu, lc);
            if (c >= 32 && c <= 64) break;
            if (c < 32) th = t; else tl = t;
            t = 0.5f * (tl + th);
        }
    }
    if (c < 32 || c > 64) {   // essentially never taken; guarantees the window
        float tl = -8.0f, th = 8.0f;
        t = 0.0f;
        for (int it = 0; it < 60; it++) {
            int lc = 0;
#pragma unroll
            for (int s = 0; s < 29; s++) lc += (v[s] > t) ? 1 : 0;
            c = __reduce_add_sync(0xffffffffu, lc);
            if (c >= 32 && c <= 64) break;
            if (c < 32) th = t; else tl = t;
            t = 0.5f * (tl + th);
        }
    }

    // compact candidates (index-ordered) into (val, idx) slots
    int base = 0;
#pragma unroll
    for (int s = 0; s < 29; s++) {
        bool p = v[s] > t;
        unsigned bal = __ballot_sync(0xffffffffu, p);
        if (p) {
            int pos = base + __popc(bal & ((1u << lane) - 1u));
            if (pos < 64) {
                s_val[warpid][pos] = v[s];
                s_idx[warpid][pos] = (unsigned short)(s * 32 + lane);
            }
        }
        base += __popc(bal);
    }
    __syncwarp();

    float s0 = (lane < c)      ? s_val[warpid][lane]      : -3.0e38f;
    float s1 = (lane + 32 < c) ? s_val[warpid][lane + 32] : -3.0e38f;

    // inner bisection on the <=64 slots: isolate exactly 32
    if (c != 32) {
        float til = t, tih = 1.6f;   // count(>til)=c>=32 ; count(>1.6)=0 always
        for (int it = 0; it < 32; it++) {
            float tm = 0.5f * (til + tih);
            int lc = ((s0 > tm) ? 1 : 0) + ((s1 > tm) ? 1 : 0);
            int cc = __reduce_add_sync(0xffffffffu, lc);
            if (cc >= 32) til = tm; else tih = tm;
            if (cc == 32) break;
        }
        t = til;
    }

    // rank = prefix count of kept slots in position (= index) order
    bool k0 = s0 > t;
    bool k1 = s1 > t;
    unsigned keep0 = __ballot_sync(0xffffffffu, k0);
    unsigned keep1 = __ballot_sync(0xffffffffu, k1);
    unsigned below = (1u << lane) - 1u;

    if (k0) {
        int r = __popc(keep0 & below);
        if (r < KK) {
            int d = (int)s_idx[warpid][lane];
            unsigned q = __float2uint_rn(myrow[d] * QSCALE);
            atomicAdd(&g_s[b * KK + r], q);
        }
    }
    if (k1) {
        int r = __popc(keep0) + __popc(keep1 & below);
        if (r < KK) {
            int d = (int)s_idx[warpid][lane + 32];
            unsigned q = __float2uint_rn(myrow[d] * QSCALE);
            atomicAdd(&g_s[b * KK + r], q);
        }
    }
}

// ---------------------------------------------------------------------------
// Fused kernel.  CTA = 4 row-pairs (b,n)/(b+32,n), 8 warps.  The threefry
// pairing (j, j+HALF) couples rows b and b+32 at equal (n,d): warps 0-3
// generate slices 0..14 for pair wp (keep row-A, export row-B via smem),
// warps 4-7 generate slices 15..28 (keep row-B, export row-A).  One sync,
// each warp completes its 29-slice register row and runs the pipeline once.
// The LAST CTA (global ticket) consumes g_s, emits the bboxes, and re-zeros
// the accumulator + ticket for the next launch / graph replay.
// ---------------------------------------------------------------------------
__global__ void __launch_bounds__(256) ftopk_kernel(const float* __restrict__ wa,
                                                    float* __restrict__ out) {
    __shared__ float s_waA[DD];
    __shared__ float s_waB[DD];
    __shared__ float ex_B[4][15][32];   // row-B values, slices 0..14
    __shared__ float ex_A[4][14][32];   // row-A values, slices 15..28
    __shared__ float s_val[8][64];
    __shared__ unsigned short s_idx[8][64];
    __shared__ bool s_last;

    int b = blockIdx.y;                 // 0..31 (pair: b and b+32)
    int warpid = threadIdx.x >> 5;
    int lane = threadIdx.x & 31;
    int wp = warpid & 3;
    bool isB = warpid >= 4;

    for (int i = threadIdx.x; i < DD; i += 256) {
        s_waA[i] = wa[b * DD + i];
        s_waB[i] = wa[(b + 32) * DD + i];
    }
    __syncthreads();

    int n = blockIdx.x * 4 + wp;        // gridDim.x = 230 -> n in [0,920)
    unsigned rowbase = (unsigned)((b * NSMP + n) * DD);  // < HALF (b < 32)

    float v[29];
    if (!isB) {
#pragma unroll
        for (int s = 0; s < 15; s++) {
            int d = s * 32 + lane;
            unsigned i = rowbase + (unsigned)d;
            uint2 r = threefry(i, i + (unsigned)HALF);
            float n0, n1;
            normals2(r.x, r.y, n0, n1);
            v[s] = s_waA[d] + 0.1f * n0;
            ex_B[wp][s][lane] = s_waB[d] + 0.1f * n1;
        }
    } else {
#pragma unroll
        for (int s = 15; s < 29; s++) {
            int d = s * 32 + lane;
            if (d < DD) {
                unsigned i = rowbase + (unsigned)d;
                uint2 r = threefry(i, i + (unsigned)HALF);
                float n0, n1;
                normals2(r.x, r.y, n0, n1);
                v[s] = s_waB[d] + 0.1f * n1;
                ex_A[wp][s - 15][lane] = s_waA[d] + 0.1f * n0;
            } else {
                v[s] = -3.0e38f;
                ex_A[wp][s - 15][lane] = -3.0e38f;
            }
        }
    }
    __syncthreads();

    if (!isB) {
#pragma unroll
        for (int s = 15; s < 29; s++) v[s] = ex_A[wp][s - 15][lane];
    } else {
#pragma unroll
        for (int s = 0; s < 15; s++) v[s] = ex_B[wp][s][lane];
    }

    process_row(v, isB ? b + 32 : b, lane, warpid, isB ? s_waB : s_waA,
                s_val, s_idx);

    // ---- last-CTA epilogue: fold g_s -> bboxes, re-arm scratch ----
    __threadfence();                    // each thread: its REDGs visible @gpu
    __syncthreads();
    if (threadIdx.x == 0) {
        unsigned tk = atomicAdd(&g_ticket, 1u);
        s_last = (tk == NCTA - 1u);
    }
    __syncthreads();
    if (s_last) {
        __threadfence();                // acquire side
        for (int idx = threadIdx.x; idx < BB * KK; idx += 256) {
            unsigned acc = atomicExch(&g_s[idx], 0u);   // read + re-zero
            float sv = __uint2float_rn(acc) * (1.0f / (QSCALE * 920.0f));
            float r  = floorf(sv / 40.0f);
            float cc = sv - 40.0f * r;                  // jnp.mod(sv, 40)
            float x0 = (cc < 1.0f ? cc : cc - 1.0f) * 32.0f;
            float y0 = (r  < 1.0f ? r  : r  - 1.0f) * 32.0f;
            float x1 = (cc < 1.0f ? cc + 2.0f : cc + 1.0f) * 32.0f;
            float y1 = (r + 2.0f) * 32.0f;
            ((float4*)out)[idx] = make_float4(x0, y0, x1, y1);
        }
        if (threadIdx.x == 0) g_ticket = 0u;            // re-arm for next launch
    }
}

// ---------------------------------------------------------------------------
extern "C" void kernel_launch(void* const* d_in, const int* in_sizes, int n_in,
                              void* d_out, int out_size) {
    const float* wa = (const float*)d_in[2];   // weight_attn (64,23,40) -> (64,920)
    float* out = (float*)d_out;                // (64,32,4) float32

    ftopk_kernel<<<dim3(NSMP / 4, BB / 2), 256>>>(wa, out);
}